// round 3
// baseline (speedup 1.0000x reference)
#include <cuda_runtime.h>
#include <cstdint>
#include <cstddef>

// Problem constants
#define TT 20
#define BB 1024
#define DD 2312

// Launch shape: persistent cooperative-style kernel.
// 128 blocks x 1024 threads, 1 block/SM (167KB smem) -> all co-resident on 148+ SMs.
#define NBLK 128
#define NTHR 1024
#define GSZ  128          // threads per row-group
#define NGRP 8            // row-groups (rows) per block: 128*8 = 1024 = B
#define NSLOT 19          // ceil(2312/128)
#define TAIL  8           // 2312 - 18*128

// Persistent device state for the software grid barrier + per-timestep
// binding-strength accumulators. All of these are restored to their initial
// values by the end of every launch (even barrier count -> sense returns to 0;
// count is reset by the last arriver; bsum slots are reset one barrier late),
// so graph replays are deterministic.
__device__ unsigned g_count = 0;
__device__ unsigned g_sense = 0;
__device__ float    g_bsum[TT];   // zero-initialized at module load

__device__ __forceinline__ float warp_max(float v) {
#pragma unroll
    for (int o = 16; o > 0; o >>= 1)
        v = fmaxf(v, __shfl_xor_sync(0xffffffffu, v, o));
    return v;
}

__device__ __forceinline__ float warp_sum(float v) {
#pragma unroll
    for (int o = 16; o > 0; o >>= 1)
        v += __shfl_xor_sync(0xffffffffu, v, o);
    return v;
}

__device__ __forceinline__ float sigmoid_fast(float xv) {
    // 1/(1+e^-x): ex2 (MUFU) + rcp (MUFU) + fma. ~2^-22 rel error.
    return 1.0f / (1.0f + __expf(-xv));
}

__global__ void __launch_bounds__(NTHR, 1)
snn_etad_kernel(const float* __restrict__ x,
                const float* __restrict__ ac,
                const float* __restrict__ tw,
                const float* __restrict__ ig,
                const float* __restrict__ p_md,
                const float* __restrict__ p_sd,
                const float* __restrict__ p_th,
                float* __restrict__ out)
{
    extern __shared__ float sm[];
    float* s_i  = sm;                 // NGRP*DD  membrane current state
    float* s_v  = s_i + NGRP * DD;    // NGRP*DD  membrane potential state
    float* s_ac = s_v + NGRP * DD;    // DD
    float* s_g  = s_ac + DD;          // DD  sigmoid(tw)*sigmoid(ig)
    float* s_rM = s_g + DD;           // 32  per-warp max
    float* s_rS = s_rM + 32;          // 32  per-warp sum(e^z)
    float* s_rW = s_rS + 32;          // 32  per-warp sum(z e^z)
    float* s_rA = s_rW + 32;          // 32  per-warp sum|c|
    float* s_bs = s_rA + 32;          // 1   broadcast binding strength

    const int tid  = threadIdx.x;
    const int grp  = tid >> 7;        // 0..7  (row within block)
    const int gtid = tid & 127;       // 0..127 (column lane within row-group)
    const int w    = tid >> 5;        // warp id 0..31
    const int lane = tid & 31;
    const int b    = blockIdx.x * NGRP + grp;   // global batch row

    const float md = p_md[0];
    const float sd = p_sd[0];
    const float th = p_th[0];
    const float inv_bd = 1.0f / (float)(BB * DD);

    // Init per-feature gates and zero the recurrent state.
    for (int idx = tid; idx < DD; idx += NTHR) {
        s_ac[idx] = ac[idx];
        s_g[idx]  = sigmoid_fast(tw[idx]) * sigmoid_fast(ig[idx]);
    }
    for (int idx = tid; idx < NGRP * DD; idx += NTHR) {
        s_i[idx] = 0.0f;
        s_v[idx] = 0.0f;
    }
    __syncthreads();

    float xr[NSLOT];   // holds x, then compressed, across the grid barrier

    for (int t = 0; t < TT; ++t) {
        // ---------- Pass B: per-row softmax entropy + compressed + |c| sum ----------
        const float* xrow = x + ((size_t)t * BB + b) * DD;

        float m = -3.402823466e38f;
#pragma unroll
        for (int s = 0; s < NSLOT; ++s) {
            const int d = s * GSZ + gtid;
            const bool act = (s < NSLOT - 1) || (gtid < TAIL);
            xr[s] = act ? __ldg(xrow + d) : -3.402823466e38f;
            m = fmaxf(m, xr[s]);
        }
        m = warp_max(m);
        if (lane == 0) s_rM[w] = m;
        __syncthreads();
        m = fmaxf(fmaxf(s_rM[grp * 4 + 0], s_rM[grp * 4 + 1]),
                  fmaxf(s_rM[grp * 4 + 2], s_rM[grp * 4 + 3]));

        float S = 0.0f, W = 0.0f;
#pragma unroll
        for (int s = 0; s < NSLOT; ++s) {
            const bool act = (s < NSLOT - 1) || (gtid < TAIL);
            if (act) {
                const float z = xr[s] - m;
                const float e = __expf(z);
                S += e;
                W += z * e;
            }
        }
        S = warp_sum(S);
        W = warp_sum(W);
        if (lane == 0) { s_rS[w] = S; s_rW[w] = W; }
        __syncthreads();
        S = s_rS[grp * 4 + 0] + s_rS[grp * 4 + 1] + s_rS[grp * 4 + 2] + s_rS[grp * 4 + 3];
        W = s_rW[grp * 4 + 0] + s_rW[grp * 4 + 1] + s_rW[grp * 4 + 2] + s_rW[grp * 4 + 3];
        // entropy = -sum p*log(p+1e-8) ~= lnS - W/S - D*1e-8  (error < 3e-6 rel)
        const float ent = __logf(S) - __fdividef(W, S) - (float)DD * 1e-8f;

        float asum = 0.0f;
#pragma unroll
        for (int s = 0; s < NSLOT; ++s) {
            const int d = s * GSZ + gtid;
            const bool act = (s < NSLOT - 1) || (gtid < TAIL);
            float c = 0.0f;
            if (act) {
                const float mk = sigmoid_fast(s_ac[d] * ent);
                c = xr[s] * mk * s_g[d];
            }
            xr[s] = c;                 // keep compressed in registers
            asum += fabsf(c);
        }
        asum = warp_sum(asum);
        if (lane == 0) s_rA[w] = asum;
        __syncthreads();

        // ---------- Global reduction + software grid barrier ----------
        if (tid == 0) {
            float tot = 0.0f;
#pragma unroll
            for (int k = 0; k < 32; ++k) tot += s_rA[k];
            atomicAdd(&g_bsum[t], tot);

            __threadfence();
            const unsigned want = (unsigned)((t + 1) & 1);
            const unsigned pos = atomicAdd(&g_count, 1);
            if (pos == NBLK - 1) {
                // Last arriver: reset counter, clean the slot consumed one
                // timestep ago (t==0 cleans slot 19 left by the previous
                // launch), then release everyone.
                atomicExch(&g_count, 0u);
                atomicExch(&g_bsum[(t + TT - 1) % TT], 0.0f);
                __threadfence();
                atomicExch(&g_sense, want);
            } else {
                while (*((volatile unsigned*)&g_sense) != want) __nanosleep(64);
                __threadfence();
            }
            const float bsv = atomicAdd(&g_bsum[t], 0.0f);  // L2-coherent read
            s_bs[0] = bsv * inv_bd;
        }
        __syncthreads();
        const float bs = s_bs[0];

        // ---------- Pass C: LIF recurrence + spike output ----------
        float* si = s_i + grp * DD;
        float* sv = s_v + grp * DD;
        float* orow = out + ((size_t)t * BB + b) * DD;
#pragma unroll
        for (int s = 0; s < NSLOT; ++s) {
            const int d = s * GSZ + gtid;
            const bool act = (s < NSLOT - 1) || (gtid < TAIL);
            if (act) {
                const float c = xr[s] * bs;
                float iv = si[d];
                iv = sd * iv + c;
                si[d] = iv;
                float vv = sv[d];
                vv = md * vv + iv;
                const float sp = 1.0f / (1.0f + __expf(th - vv));  // sigmoid(v-th)
                vv -= sp * th;
                sv[d] = vv;
                orow[d] = sp;
            }
        }
        // No extra bar needed: next iteration's first smem write (s_rM) is
        // followed by a __syncthreads before any read, and all reads of the
        // reduction buffers completed before the barrier above.
    }
}

extern "C" void kernel_launch(void* const* d_in, const int* in_sizes, int n_in,
                              void* d_out, int out_size)
{
    (void)in_sizes; (void)n_in; (void)out_size;
    const float* x  = (const float*)d_in[0];
    const float* ac = (const float*)d_in[1];
    const float* tw = (const float*)d_in[2];
    const float* ig = (const float*)d_in[3];
    const float* md = (const float*)d_in[4];
    const float* sd = (const float*)d_in[5];
    const float* th = (const float*)d_in[6];
    float* out = (float*)d_out;

    constexpr size_t SMEM_FLOATS =
        (size_t)2 * NGRP * DD + 2 * DD + 4 * 32 + 1;
    constexpr size_t SMEM_BYTES = SMEM_FLOATS * sizeof(float);  // ~166,980 B

    cudaFuncSetAttribute(snn_etad_kernel,
                         cudaFuncAttributeMaxDynamicSharedMemorySize,
                         (int)SMEM_BYTES);

    snn_etad_kernel<<<NBLK, NTHR, SMEM_BYTES>>>(x, ac, tw, ig, md, sd, th, out);
}

// round 4
// speedup vs baseline: 1.2919x; 1.2919x over previous
#include <cuda_runtime.h>
#include <cstdint>
#include <cstddef>

// Problem constants
#define TT 20
#define BB 1024
#define DD 2312
#define D4 578            // DD / 4, exact

// Persistent kernel: 128 blocks x 1024 threads, 1 block/SM (smem ~167KB).
#define NBLK 128
#define NTHR 1024
#define GSZ  128          // threads per row-group
#define NGRP 8            // rows per block
#define NS4  5            // ceil(578/128) float4 slots per thread
#define TAIL4 66          // 578 - 4*128

#define L2E 1.4426950408889634f

// Grid barrier + per-timestep binding-strength accumulators. All restored to
// initial values by end of launch (20 barriers = even -> sense returns to 0;
// count reset by last arriver; bsum slots cleaned one barrier late), so graph
// replays are deterministic.
__device__ unsigned g_count = 0;
__device__ unsigned g_sense = 0;
__device__ float    g_bsum[TT];

__device__ __forceinline__ float warp_sum(float v) {
#pragma unroll
    for (int o = 16; o > 0; o >>= 1)
        v += __shfl_xor_sync(0xffffffffu, v, o);
    return v;
}

__device__ __forceinline__ float ex2a(float x) {
    float y;
    asm("ex2.approx.ftz.f32 %0, %1;" : "=f"(y) : "f"(x));
    return y;
}

__device__ __forceinline__ float rcpa(float x) {
    float y;
    asm("rcp.approx.ftz.f32 %0, %1;" : "=f"(y) : "f"(x));
    return y;
}

// fast sigmoid: 1/(1+2^(-x*log2e))  (2 MUFU + 1 FMA + 1 ADD)
__device__ __forceinline__ float sigm(float x) {
    return rcpa(1.0f + ex2a(-x * L2E));
}

__global__ void __launch_bounds__(NTHR, 1)
snn_etad_kernel(const float* __restrict__ x,
                const float* __restrict__ ac,
                const float* __restrict__ tw,
                const float* __restrict__ ig,
                const float* __restrict__ p_md,
                const float* __restrict__ p_sd,
                const float* __restrict__ p_th,
                float* __restrict__ out)
{
    extern __shared__ float sm[];
    float* s_i  = sm;                  // NGRP*DD
    float* s_v  = s_i + NGRP * DD;     // NGRP*DD
    float* s_ac = s_v + NGRP * DD;     // DD
    float* s_g  = s_ac + DD;           // DD
    float* s_rS = s_g + DD;            // 32 per-warp sum(e^x)
    float* s_rW = s_rS + 32;           // 32 per-warp sum(x e^x)
    float* s_rA = s_rW + 32;           // 32 per-warp sum|c|
    float* s_bs = s_rA + 32;           // 1

    const int tid  = threadIdx.x;
    const int grp  = tid >> 7;         // row within block
    const int gtid = tid & 127;        // lane within row-group
    const int w    = tid >> 5;
    const int lane = tid & 31;
    const int b    = blockIdx.x * NGRP + grp;

    const float md = p_md[0];
    const float sd = p_sd[0];
    const float th = p_th[0];
    const float inv_bd = 1.0f / (float)(BB * DD);

    for (int idx = tid; idx < DD; idx += NTHR) {
        s_ac[idx] = ac[idx];
        s_g[idx]  = sigm(tw[idx]) * sigm(ig[idx]);
    }
    for (int idx = tid; idx < NGRP * DD; idx += NTHR) {
        s_i[idx] = 0.0f;
        s_v[idx] = 0.0f;
    }
    __syncthreads();

    const float4* ac4 = (const float4*)s_ac;
    const float4* g4  = (const float4*)s_g;
    float4* si4 = ((float4*)s_i) + grp * D4;
    float4* sv4 = ((float4*)s_v) + grp * D4;

    float4 xv[NS4];   // x, then compressed, held in registers

    for (int t = 0; t < TT; ++t) {
        const float4* xrow4 = (const float4*)(x + ((size_t)t * BB + b) * DD);

        // ---- Pass 1: load x (float4) + accumulate S = sum e^x, W = sum x e^x
        // (max-subtraction dropped: entropy = lnS - W/S is shift-invariant and
        //  |x| < ~6 so no overflow)
        float S = 0.0f, W = 0.0f;
#pragma unroll
        for (int s = 0; s < NS4; ++s) {
            const int d4 = s * GSZ + gtid;
            const bool act = (s < NS4 - 1) || (gtid < TAIL4);
            if (act) {
                const float4 v = __ldg(xrow4 + d4);
                xv[s] = v;
                float e;
                e = ex2a(v.x * L2E); S += e; W += v.x * e;
                e = ex2a(v.y * L2E); S += e; W += v.y * e;
                e = ex2a(v.z * L2E); S += e; W += v.z * e;
                e = ex2a(v.w * L2E); S += e; W += v.w * e;
            }
        }
        S = warp_sum(S);
        W = warp_sum(W);
        if (lane == 0) { s_rS[w] = S; s_rW[w] = W; }
        // group-local barrier (4 warps of this row only)
        asm volatile("bar.sync %0, %1;" :: "r"(grp + 1), "n"(GSZ) : "memory");
        S = s_rS[grp * 4 + 0] + s_rS[grp * 4 + 1] + s_rS[grp * 4 + 2] + s_rS[grp * 4 + 3];
        W = s_rW[grp * 4 + 0] + s_rW[grp * 4 + 1] + s_rW[grp * 4 + 2] + s_rW[grp * 4 + 3];
        const float ent = __logf(S) - __fdividef(W, S) - (float)DD * 1e-8f;

        // ---- Pass 2: compression mask + gates, accumulate sum|c|
        float asum = 0.0f;
#pragma unroll
        for (int s = 0; s < NS4; ++s) {
            const int d4 = s * GSZ + gtid;
            const bool act = (s < NS4 - 1) || (gtid < TAIL4);
            if (act) {
                const float4 a = ac4[d4];
                const float4 g = g4[d4];
                float4 c = xv[s];
                c.x = c.x * sigm(a.x * ent) * g.x;
                c.y = c.y * sigm(a.y * ent) * g.y;
                c.z = c.z * sigm(a.z * ent) * g.z;
                c.w = c.w * sigm(a.w * ent) * g.w;
                xv[s] = c;
                asum += fabsf(c.x) + fabsf(c.y) + fabsf(c.z) + fabsf(c.w);
            }
        }
        asum = warp_sum(asum);
        if (lane == 0) s_rA[w] = asum;
        __syncthreads();

        // ---- Global mean|c| + software grid barrier
        if (tid == 0) {
            float tot = 0.0f;
#pragma unroll
            for (int k = 0; k < 32; ++k) tot += s_rA[k];
            atomicAdd(&g_bsum[t], tot);

            __threadfence();
            const unsigned want = (unsigned)((t + 1) & 1);
            const unsigned pos = atomicAdd(&g_count, 1);
            if (pos == NBLK - 1) {
                atomicExch(&g_count, 0u);
                atomicExch(&g_bsum[(t + TT - 1) % TT], 0.0f);  // clean stale slot
                __threadfence();
                atomicExch(&g_sense, want);
            } else {
                while (*((volatile unsigned*)&g_sense) != want) __nanosleep(64);
                __threadfence();
            }
            const float bsv = atomicAdd(&g_bsum[t], 0.0f);  // coherent read
            s_bs[0] = bsv * inv_bd;
        }
        __syncthreads();
        const float bs = s_bs[0];

        // ---- Pass 3: LIF recurrence + spike output (all float4)
        float4* o4 = (float4*)(out + ((size_t)t * BB + b) * DD);
#pragma unroll
        for (int s = 0; s < NS4; ++s) {
            const int d4 = s * GSZ + gtid;
            const bool act = (s < NS4 - 1) || (gtid < TAIL4);
            if (act) {
                const float4 c = xv[s];
                float4 iv = si4[d4];
                float4 vv = sv4[d4];
                float4 sp;

                iv.x = sd * iv.x + c.x * bs;
                vv.x = md * vv.x + iv.x;
                sp.x = sigm(vv.x - th);
                vv.x -= sp.x * th;

                iv.y = sd * iv.y + c.y * bs;
                vv.y = md * vv.y + iv.y;
                sp.y = sigm(vv.y - th);
                vv.y -= sp.y * th;

                iv.z = sd * iv.z + c.z * bs;
                vv.z = md * vv.z + iv.z;
                sp.z = sigm(vv.z - th);
                vv.z -= sp.z * th;

                iv.w = sd * iv.w + c.w * bs;
                vv.w = md * vv.w + iv.w;
                sp.w = sigm(vv.w - th);
                vv.w -= sp.w * th;

                si4[d4] = iv;
                sv4[d4] = vv;
                o4[d4]  = sp;
            }
        }
        // Next iteration's first smem write (s_rS) by warp w happens after this
        // warp passed both __syncthreads above; other warps' reads of s_rS[w]
        // for step t also happened before those barriers. No extra sync needed.
    }
}

extern "C" void kernel_launch(void* const* d_in, const int* in_sizes, int n_in,
                              void* d_out, int out_size)
{
    (void)in_sizes; (void)n_in; (void)out_size;
    const float* x  = (const float*)d_in[0];
    const float* ac = (const float*)d_in[1];
    const float* tw = (const float*)d_in[2];
    const float* ig = (const float*)d_in[3];
    const float* md = (const float*)d_in[4];
    const float* sd = (const float*)d_in[5];
    const float* th = (const float*)d_in[6];
    float* out = (float*)d_out;

    constexpr size_t SMEM_FLOATS =
        (size_t)2 * NGRP * DD + 2 * DD + 3 * 32 + 1;
    constexpr size_t SMEM_BYTES = SMEM_FLOATS * sizeof(float);

    cudaFuncSetAttribute(snn_etad_kernel,
                         cudaFuncAttributeMaxDynamicSharedMemorySize,
                         (int)SMEM_BYTES);

    snn_etad_kernel<<<NBLK, NTHR, SMEM_BYTES>>>(x, ac, tw, ig, md, sd, th, out);
}

// round 5
// speedup vs baseline: 1.4715x; 1.1390x over previous
#include <cuda_runtime.h>
#include <cstdint>
#include <cstddef>

// Problem constants
#define TT 20
#define BB 1024
#define DD 2312
#define D4 578            // DD / 4, exact

// Persistent kernel: 128 blocks x 1024 threads, 1 block/SM (smem ~167KB).
#define NBLK 128
#define NTHR 1024
#define GSZ  128          // threads per row-group
#define NGRP 8            // rows per block
#define NS4  5            // ceil(578/128) float4 slots per thread
#define TAIL4 66          // 578 - 4*128

#define L2E 1.4426950408889634f

// Grid barrier + per-timestep binding-strength accumulators. All restored to
// initial values by end of launch (20 flips -> sense returns to 0; count reset
// by last arriver; bsum slots cleaned one barrier late), so graph replays are
// deterministic.
__device__ unsigned g_count = 0;
__device__ unsigned g_sense = 0;
__device__ float    g_bsum[TT];

__device__ __forceinline__ float warp_sum(float v) {
#pragma unroll
    for (int o = 16; o > 0; o >>= 1)
        v += __shfl_xor_sync(0xffffffffu, v, o);
    return v;
}

__device__ __forceinline__ float ex2a(float x) {
    float y;
    asm("ex2.approx.ftz.f32 %0, %1;" : "=f"(y) : "f"(x));
    return y;
}

__device__ __forceinline__ float rcpa(float x) {
    float y;
    asm("rcp.approx.ftz.f32 %0, %1;" : "=f"(y) : "f"(x));
    return y;
}

__device__ __forceinline__ float tanha(float x) {
    float y;
    asm("tanh.approx.f32 %0, %1;" : "=f"(y) : "f"(x));
    return y;
}

// exact-path sigmoid (2 MUFU) — used for spike output where error is direct
__device__ __forceinline__ float sigm(float x) {
    return rcpa(1.0f + ex2a(-x * L2E));
}

// cheap sigmoid via tanh (1 MUFU) — used for the compression mask, whose
// error is attenuated ~1e4x before reaching the output
__device__ __forceinline__ float sigm_t(float x) {
    return fmaf(0.5f, tanha(0.5f * x), 0.5f);
}

__device__ __forceinline__ void pref_l2(const void* p) {
    asm volatile("prefetch.global.L2 [%0];" :: "l"(p));
}

__global__ void __launch_bounds__(NTHR, 1)
snn_etad_kernel(const float* __restrict__ x,
                const float* __restrict__ ac,
                const float* __restrict__ tw,
                const float* __restrict__ ig,
                const float* __restrict__ p_md,
                const float* __restrict__ p_sd,
                const float* __restrict__ p_th,
                float* __restrict__ out)
{
    extern __shared__ float sm[];
    float* s_i  = sm;                  // NGRP*DD
    float* s_v  = s_i + NGRP * DD;     // NGRP*DD
    float* s_ac = s_v + NGRP * DD;     // DD
    float* s_g  = s_ac + DD;           // DD
    float* s_rS = s_g + DD;            // 32 per-warp sum(e^x)
    float* s_rW = s_rS + 32;           // 32 per-warp sum(x e^x)
    float* s_rA = s_rW + 32;           // 32 per-warp sum|c|
    float* s_bsv = s_rA + 32;          // 1  published binding strength
    int*   s_step = (int*)(s_bsv + 1); // 1  monotonic publish counter

    const int tid  = threadIdx.x;
    const int grp  = tid >> 7;         // row within block
    const int gtid = tid & 127;        // lane within row-group
    const int w    = tid >> 5;
    const int lane = tid & 31;
    const int b    = blockIdx.x * NGRP + grp;

    const float md = p_md[0];
    const float sd = p_sd[0];
    const float th = p_th[0];
    const float inv_bd = 1.0f / (float)(BB * DD);

    for (int idx = tid; idx < DD; idx += NTHR) {
        s_ac[idx] = ac[idx];
        s_g[idx]  = sigm(tw[idx]) * sigm(ig[idx]);
    }
    for (int idx = tid; idx < NGRP * DD; idx += NTHR) {
        s_i[idx] = 0.0f;
        s_v[idx] = 0.0f;
    }
    if (tid == 0) *(volatile int*)s_step = 0;
    __syncthreads();

    const float4* ac4 = (const float4*)s_ac;
    const float4* g4  = (const float4*)s_g;
    float4* si4 = ((float4*)s_i) + grp * D4;
    float4* sv4 = ((float4*)s_v) + grp * D4;

    float4 xv[NS4];   // x, then compressed, held in registers

    for (int t = 0; t < TT; ++t) {
        const float4* xrow4 = (const float4*)(x + ((size_t)t * BB + b) * DD);

        // ---- Pass 1: load x (float4) + S = sum e^x, W = sum x e^x
        // (shift-invariant entropy: lnS - W/S; |x| < ~6 so no overflow)
        float S = 0.0f, W = 0.0f;
#pragma unroll
        for (int s = 0; s < NS4; ++s) {
            const int d4 = s * GSZ + gtid;
            const bool act = (s < NS4 - 1) || (gtid < TAIL4);
            if (act) {
                const float4 v = __ldg(xrow4 + d4);
                xv[s] = v;
                float e;
                e = ex2a(v.x * L2E); S += e; W += v.x * e;
                e = ex2a(v.y * L2E); S += e; W += v.y * e;
                e = ex2a(v.z * L2E); S += e; W += v.z * e;
                e = ex2a(v.w * L2E); S += e; W += v.w * e;
            }
        }
        S = warp_sum(S);
        W = warp_sum(W);
        if (lane == 0) { s_rS[w] = S; s_rW[w] = W; }
        asm volatile("bar.sync %0, %1;" :: "r"(grp + 1), "n"(GSZ) : "memory");
        S = s_rS[grp * 4 + 0] + s_rS[grp * 4 + 1] + s_rS[grp * 4 + 2] + s_rS[grp * 4 + 3];
        W = s_rW[grp * 4 + 0] + s_rW[grp * 4 + 1] + s_rW[grp * 4 + 2] + s_rW[grp * 4 + 3];
        const float ent = __logf(S) - __fdividef(W, S) - (float)DD * 1e-8f;

        // ---- Pass 2: compression mask (tanh-sigmoid) + gates, sum|c|
        float asum = 0.0f;
#pragma unroll
        for (int s = 0; s < NS4; ++s) {
            const int d4 = s * GSZ + gtid;
            const bool act = (s < NS4 - 1) || (gtid < TAIL4);
            if (act) {
                const float4 a = ac4[d4];
                const float4 g = g4[d4];
                float4 c = xv[s];
                c.x = c.x * sigm_t(a.x * ent) * g.x;
                c.y = c.y * sigm_t(a.y * ent) * g.y;
                c.z = c.z * sigm_t(a.z * ent) * g.z;
                c.w = c.w * sigm_t(a.w * ent) * g.w;
                xv[s] = c;
                asum += fabsf(c.x) + fabsf(c.y) + fabsf(c.z) + fabsf(c.w);
            }
        }
        asum = warp_sum(asum);
        if (lane == 0) s_rA[w] = asum;

        // ---- Prefetch next timestep's x into L2 during the barrier window
        if (t < TT - 1) {
            const float4* xnext = xrow4 + (size_t)BB * D4;
#pragma unroll
            for (int s = 0; s < NS4; ++s) {
                const int d4 = s * GSZ + gtid;
                const bool act = (s < NS4 - 1) || (gtid < TAIL4);
                if (act) pref_l2(xnext + d4);
            }
        }

        __syncthreads();   // s_rA complete

        // ---- Global mean|c| + software grid barrier (tid0 only)
        if (tid == 0) {
            float tot = 0.0f;
#pragma unroll
            for (int k = 0; k < 32; ++k) tot += s_rA[k];
            atomicAdd(&g_bsum[t], tot);

            __threadfence();
            const unsigned want = (unsigned)((t + 1) & 1);
            const unsigned pos = atomicAdd(&g_count, 1);
            if (pos == NBLK - 1) {
                atomicExch(&g_count, 0u);
                atomicExch(&g_bsum[(t + TT - 1) % TT], 0.0f);  // clean stale slot
                __threadfence();
                atomicExch(&g_sense, want);
            } else {
                while (*((volatile unsigned*)&g_sense) != want) __nanosleep(32);
                __threadfence();
            }
            const float bsv = atomicAdd(&g_bsum[t], 0.0f);  // coherent read
            *(volatile float*)s_bsv = bsv * inv_bd;
            __threadfence_block();
            *(volatile int*)s_step = t + 1;                 // publish
        }

        // ---- Per-warp pickup: no block-wide reconvergence, warps stagger
        float bs;
        if (lane == 0) {
            while (*(volatile int*)s_step < t + 1) { }
            bs = *(volatile float*)s_bsv;
        }
        bs = __shfl_sync(0xffffffffu, bs, 0);

        // ---- Pass 3: LIF recurrence + spike output (float4)
        float4* o4 = (float4*)(out + ((size_t)t * BB + b) * DD);
#pragma unroll
        for (int s = 0; s < NS4; ++s) {
            const int d4 = s * GSZ + gtid;
            const bool act = (s < NS4 - 1) || (gtid < TAIL4);
            if (act) {
                const float4 c = xv[s];
                float4 iv = si4[d4];
                float4 vv = sv4[d4];
                float4 sp;

                iv.x = sd * iv.x + c.x * bs;
                vv.x = md * vv.x + iv.x;
                sp.x = sigm(vv.x - th);
                vv.x -= sp.x * th;

                iv.y = sd * iv.y + c.y * bs;
                vv.y = md * vv.y + iv.y;
                sp.y = sigm(vv.y - th);
                vv.y -= sp.y * th;

                iv.z = sd * iv.z + c.z * bs;
                vv.z = md * vv.z + iv.z;
                sp.z = sigm(vv.z - th);
                vv.z -= sp.z * th;

                iv.w = sd * iv.w + c.w * bs;
                vv.w = md * vv.w + iv.w;
                sp.w = sigm(vv.w - th);
                vv.w -= sp.w * th;

                si4[d4] = iv;
                sv4[d4] = vv;
                o4[d4]  = sp;
            }
        }
        // Safety of smem buffer reuse across steps without a trailing barrier:
        // - s_rS/s_rW[w] at t+1 are written by warp w only after its poll of
        //   step t succeeded; every reader of those slots at step t (its own
        //   row-group) finished reading before arriving at __syncthreads(t),
        //   which precedes the global release that gates warp w's poll.
        // - s_rA[w] at t+1: its only reader (tid0 at step t) read it before
        //   contributing to the barrier whose release gates warp w.
        // - s_bsv/s_step are monotonic within a launch.
    }
}

extern "C" void kernel_launch(void* const* d_in, const int* in_sizes, int n_in,
                              void* d_out, int out_size)
{
    (void)in_sizes; (void)n_in; (void)out_size;
    const float* x  = (const float*)d_in[0];
    const float* ac = (const float*)d_in[1];
    const float* tw = (const float*)d_in[2];
    const float* ig = (const float*)d_in[3];
    const float* md = (const float*)d_in[4];
    const float* sd = (const float*)d_in[5];
    const float* th = (const float*)d_in[6];
    float* out = (float*)d_out;

    constexpr size_t SMEM_FLOATS =
        (size_t)2 * NGRP * DD + 2 * DD + 3 * 32 + 2;
    constexpr size_t SMEM_BYTES = SMEM_FLOATS * sizeof(float);

    cudaFuncSetAttribute(snn_etad_kernel,
                         cudaFuncAttributeMaxDynamicSharedMemorySize,
                         (int)SMEM_BYTES);

    snn_etad_kernel<<<NBLK, NTHR, SMEM_BYTES>>>(x, ac, tw, ig, md, sd, th, out);
}

// round 7
// speedup vs baseline: 1.5310x; 1.0405x over previous
#include <cuda_runtime.h>
#include <cuda_fp16.h>
#include <cstdint>
#include <cstddef>

// Problem constants
#define TT 20
#define BB 1024
#define DD 2312
#define D4 578            // DD / 4, exact

// Persistent kernel: 128 blocks x 1024 threads, 1 block/SM (~199KB smem).
#define NBLK 128
#define NTHR 1024
#define GSZ  128          // threads per row-group
#define NGRP 8            // rows per block
#define NS4  5            // ceil(578/128) float4 slots per thread
#define TAIL4 66          // 578 - 4*128

#define L2E 1.4426950408889634f

// Grid barrier + per-timestep binding-strength accumulators. Restored to
// initial values every launch (20 sense flips -> back to 0; count reset by the
// last arriver; bsum slots cleaned one barrier late) -> graph replays are
// deterministic.
__device__ unsigned g_count = 0;
__device__ unsigned g_sense = 0;
__device__ float    g_bsum[TT];

__device__ __forceinline__ float warp_sum(float v) {
#pragma unroll
    for (int o = 16; o > 0; o >>= 1)
        v += __shfl_xor_sync(0xffffffffu, v, o);
    return v;
}

__device__ __forceinline__ float ex2a(float x) {
    float y; asm("ex2.approx.ftz.f32 %0, %1;" : "=f"(y) : "f"(x)); return y;
}
__device__ __forceinline__ float rcpa(float x) {
    float y; asm("rcp.approx.ftz.f32 %0, %1;" : "=f"(y) : "f"(x)); return y;
}
__device__ __forceinline__ float tanha(float x) {
    float y; asm("tanh.approx.f32 %0, %1;" : "=f"(y) : "f"(x)); return y;
}
// exact-path sigmoid (2 MUFU) — spike output, error lands directly on out
__device__ __forceinline__ float sigm(float x) {
    return rcpa(1.0f + ex2a(-x * L2E));
}
// cheap sigmoid via tanh (1 MUFU) — compression mask, error attenuated ~1e4x
__device__ __forceinline__ float sigm_t(float x) {
    return fmaf(0.5f, tanha(0.5f * x), 0.5f);
}

// want(k) for barrier k: sense value the k-th release sets
__device__ __forceinline__ unsigned want_of(int k) { return (unsigned)((k + 1) & 1); }

__global__ void __launch_bounds__(NTHR, 1)
snn_etad_kernel(const float* __restrict__ x,
                const float* __restrict__ ac,
                const float* __restrict__ tw,
                const float* __restrict__ ig,
                const float* __restrict__ p_md,
                const float* __restrict__ p_sd,
                const float* __restrict__ p_th,
                float* __restrict__ out)
{
    extern __shared__ float sm[];
    float*   s_i  = sm;                       // NGRP*DD floats
    float*   s_v  = s_i + NGRP * DD;          // NGRP*DD floats
    float*   s_ac = s_v + NGRP * DD;          // DD floats
    float*   s_g  = s_ac + DD;                // DD floats
    __half2* s_c  = (__half2*)(s_g + DD);     // NGRP*D4*2 half2 = NGRP*D4*2 floats worth
    float*   s_rA = (float*)(s_c + NGRP * D4 * 2);  // 2 x 32 ping-pong |c| sums
    float*   s_bsv = s_rA + 64;               // 1
    volatile int* s_step = (volatile int*)(s_bsv + 1);  // 1 monotonic publish
    float*   s_rS = (float*)(s_step + 1);     // 32
    float*   s_rW = s_rS + 32;                // 32

    const int tid  = threadIdx.x;
    const int grp  = tid >> 7;
    const int gtid = tid & 127;
    const int w    = tid >> 5;
    const int lane = tid & 31;
    const int b    = blockIdx.x * NGRP + grp;

    const float md = p_md[0];
    const float sd = p_sd[0];
    const float th = p_th[0];
    const float inv_bd = 1.0f / (float)(BB * DD);

    for (int idx = tid; idx < DD; idx += NTHR) {
        s_ac[idx] = ac[idx];
        s_g[idx]  = sigm(tw[idx]) * sigm(ig[idx]);
    }
    for (int idx = tid; idx < NGRP * DD; idx += NTHR) {
        s_i[idx] = 0.0f;
        s_v[idx] = 0.0f;
    }
    if (tid == 0) *s_step = 0;
    __syncthreads();

    const float4* ac4 = (const float4*)s_ac;
    const float4* g4  = (const float4*)s_g;
    float4*  si4 = ((float4*)s_i) + grp * D4;
    float4*  sv4 = ((float4*)s_v) + grp * D4;
    __half2* sc2 = s_c + grp * D4 * 2;

    float4 xv[NS4];   // x(t+1) -> c(t+1), registers

    // ============ pass1+pass2 for timestep t: fills xv with c, returns warp asum
    auto compute_c = [&](int t) -> float {
        const float4* xrow4 = (const float4*)(x + ((size_t)t * BB + b) * DD);
        float S = 0.0f, W = 0.0f;
#pragma unroll
        for (int s = 0; s < NS4; ++s) {
            const int d4 = s * GSZ + gtid;
            const bool act = (s < NS4 - 1) || (gtid < TAIL4);
            if (act) {
                const float4 v = __ldg(xrow4 + d4);
                xv[s] = v;
                float e;
                e = ex2a(v.x * L2E); S += e; W += v.x * e;
                e = ex2a(v.y * L2E); S += e; W += v.y * e;
                e = ex2a(v.z * L2E); S += e; W += v.z * e;
                e = ex2a(v.w * L2E); S += e; W += v.w * e;
            }
        }
        S = warp_sum(S);
        W = warp_sum(W);
        if (lane == 0) { s_rS[w] = S; s_rW[w] = W; }
        asm volatile("bar.sync %0, %1;" :: "r"(grp + 1), "n"(GSZ) : "memory");
        S = s_rS[grp * 4 + 0] + s_rS[grp * 4 + 1] + s_rS[grp * 4 + 2] + s_rS[grp * 4 + 3];
        W = s_rW[grp * 4 + 0] + s_rW[grp * 4 + 1] + s_rW[grp * 4 + 2] + s_rW[grp * 4 + 3];
        const float ent = __logf(S) - __fdividef(W, S) - (float)DD * 1e-8f;

        float asum = 0.0f;
#pragma unroll
        for (int s = 0; s < NS4; ++s) {
            const int d4 = s * GSZ + gtid;
            const bool act = (s < NS4 - 1) || (gtid < TAIL4);
            if (act) {
                const float4 a = ac4[d4];
                const float4 g = g4[d4];
                float4 c = xv[s];
                c.x = c.x * sigm_t(a.x * ent) * g.x;
                c.y = c.y * sigm_t(a.y * ent) * g.y;
                c.z = c.z * sigm_t(a.z * ent) * g.z;
                c.w = c.w * sigm_t(a.w * ent) * g.w;
                xv[s] = c;
                asum += fabsf(c.x) + fabsf(c.y) + fabsf(c.z) + fabsf(c.w);
            }
        }
        return warp_sum(asum);
    };

    // ============ block-level |c| sum -> s_rA ping-pong + sync + warp0 reduce
    auto post_asum = [&](int k, float asum) -> float {
        if (lane == 0) s_rA[((unsigned)k & 1) * 32 + w] = asum;
        __syncthreads();
        float tot = 0.0f;
        if (w == 0) tot = warp_sum(s_rA[((unsigned)k & 1) * 32 + lane]);
        return tot;  // valid in warp 0 only
    };

    // ============ tid0: arrive at global barrier k with this block's total
    auto arrive = [&](int k, float tot) {
        atomicAdd(&g_bsum[k], tot);
        __threadfence();
        const unsigned pos = atomicAdd(&g_count, 1);
        if (pos == NBLK - 1) {
            atomicExch(&g_count, 0u);
            atomicExch(&g_bsum[(k + TT - 1) % TT], 0.0f);   // clean stale slot
            __threadfence();
            atomicExch(&g_sense, want_of(k));
        }
    };

    // ---------------- prologue: c(0) -> smem, arrive(0)
    {
        float asum = compute_c(0);
        float tot = post_asum(0, asum);
#pragma unroll
        for (int s = 0; s < NS4; ++s) {
            const int d4 = s * GSZ + gtid;
            const bool act = (s < NS4 - 1) || (gtid < TAIL4);
            if (act) {
                const float4 c = xv[s];
                sc2[d4 * 2 + 0] = __floats2half2_rn(c.x, c.y);
                sc2[d4 * 2 + 1] = __floats2half2_rn(c.z, c.w);
            }
        }
        if (tid == 0) arrive(0, tot);
    }

    for (int t = 0; t < TT; ++t) {
        // ---- pass1+2 for t+1 (independent of bs(t)) — hides barrier latency
        float tot = 0.0f;
        const bool has_next = (t + 1) < TT;
        if (has_next) {
            float asum = compute_c(t + 1);
            tot = post_asum(t + 1, asum);
        } else {
            __syncthreads();   // order final s_c reads vs its writers
        }

        // ---- tid0: wait barrier t (released ~1 compute-iteration ago),
        //      publish bs(t), then arrive barrier t+1
        if (tid == 0) {
            const unsigned want = want_of(t);
            while (*((volatile unsigned*)&g_sense) != want) __nanosleep(32);
            __threadfence();
            const float bsv = atomicAdd(&g_bsum[t], 0.0f);   // coherent read
            *(volatile float*)s_bsv = bsv * inv_bd;
            __threadfence_block();
            *s_step = t + 1;                                  // publish
            if (has_next) arrive(t + 1, tot);
        }

        // ---- per-warp pickup (warps stagger straight into pass3)
        float bs;
        if (lane == 0) {
            while (*s_step < t + 1) { }
            bs = *(volatile float*)s_bsv;
        }
        bs = __shfl_sync(0xffffffffu, bs, 0);

        // ---- pass3: LIF on c(t) from smem fp16; then overwrite the slot with
        //      c(t+1) from registers (thread-private slot -> no extra sync)
        float4* o4 = (float4*)(out + ((size_t)t * BB + b) * DD);
#pragma unroll
        for (int s = 0; s < NS4; ++s) {
            const int d4 = s * GSZ + gtid;
            const bool act = (s < NS4 - 1) || (gtid < TAIL4);
            if (act) {
                const float2 c01 = __half22float2(sc2[d4 * 2 + 0]);
                const float2 c23 = __half22float2(sc2[d4 * 2 + 1]);
                float4 iv = si4[d4];
                float4 vv = sv4[d4];
                float4 sp;

                iv.x = sd * iv.x + c01.x * bs;
                vv.x = md * vv.x + iv.x;
                sp.x = sigm(vv.x - th);
                vv.x -= sp.x * th;

                iv.y = sd * iv.y + c01.y * bs;
                vv.y = md * vv.y + iv.y;
                sp.y = sigm(vv.y - th);
                vv.y -= sp.y * th;

                iv.z = sd * iv.z + c23.x * bs;
                vv.z = md * vv.z + iv.z;
                sp.z = sigm(vv.z - th);
                vv.z -= sp.z * th;

                iv.w = sd * iv.w + c23.y * bs;
                vv.w = md * vv.w + iv.w;
                sp.w = sigm(vv.w - th);
                vv.w -= sp.w * th;

                si4[d4] = iv;
                sv4[d4] = vv;
                __stcs(o4 + d4, sp);

                if (has_next) {
                    const float4 cn = xv[s];
                    sc2[d4 * 2 + 0] = __floats2half2_rn(cn.x, cn.y);
                    sc2[d4 * 2 + 1] = __floats2half2_rn(cn.z, cn.w);
                }
            }
        }
        // smem reuse safety across steps:
        // - s_rS/s_rW writes at step k+1 happen after this warp's s_step poll
        //   for step k passed; their step-k readers (same row-group) finished
        //   before the __syncthreads inside post_asum(k).
        // - s_rA is ping-ponged; same slot rewritten only two barriers later.
        // - s_c slots are strictly thread-private.
        // - s_bsv/s_step are monotonic within a launch.
    }
}

extern "C" void kernel_launch(void* const* d_in, const int* in_sizes, int n_in,
                              void* d_out, int out_size)
{
    (void)in_sizes; (void)n_in; (void)out_size;
    const float* x  = (const float*)d_in[0];
    const float* ac = (const float*)d_in[1];
    const float* tw = (const float*)d_in[2];
    const float* ig = (const float*)d_in[3];
    const float* md = (const float*)d_in[4];
    const float* sd = (const float*)d_in[5];
    const float* th = (const float*)d_in[6];
    float* out = (float*)d_out;

    // floats: i,v (2*8*2312=36992) + ac,g (2*2312=4624)
    //         + c: NGRP*D4*2 half2 = 9248 half2 = 36992 B = 9248 float-equiv
    //         + rA(64) + bsv(1) + step(1) + rS(32) + rW(32)
    constexpr size_t SMEM_FLOATS =
        (size_t)2 * NGRP * DD + 2 * DD + (size_t)NGRP * D4 * 2 + 64 + 2 + 64;
    constexpr size_t SMEM_BYTES = SMEM_FLOATS * sizeof(float);  // 203,976 B

    cudaFuncSetAttribute(snn_etad_kernel,
                         cudaFuncAttributeMaxDynamicSharedMemorySize,
                         (int)SMEM_BYTES);

    snn_etad_kernel<<<NBLK, NTHR, SMEM_BYTES>>>(x, ac, tw, ig, md, sd, th, out);
}

// round 8
// speedup vs baseline: 1.7561x; 1.1470x over previous
#include <cuda_runtime.h>
#include <cuda_fp16.h>
#include <cstdint>
#include <cstddef>

// Problem constants
#define TT 20
#define BB 1024
#define DD 2312
#define D4 578            // DD / 4, exact

// Persistent kernel: 147 blocks x 896 threads, 1 block/SM (~74.5KB smem).
// Blocks 0..145 own 7 rows each (rows 7b..7b+6); block 146 owns rows 1022..1023.
#define NBLK 147
#define NTHR 896
#define GSZ  128          // threads per row-group
#define NGRP 7            // max rows per block
#define NS4  5            // ceil(578/128) float4 slots per thread
#define TAIL4 66          // 578 - 4*128

#define L2E 1.4426950408889634f

// Grid barrier + per-timestep binding-strength accumulators. Restored to
// initial values every launch (20 sense flips -> back to 0; count reset by the
// last arriver; bsum slots cleaned one barrier late) -> graph replays are
// deterministic.
__device__ unsigned g_count = 0;
__device__ unsigned g_sense = 0;
__device__ float    g_bsum[TT];

__device__ __forceinline__ float warp_sum(float v) {
#pragma unroll
    for (int o = 16; o > 0; o >>= 1)
        v += __shfl_xor_sync(0xffffffffu, v, o);
    return v;
}

__device__ __forceinline__ float ex2a(float x) {
    float y; asm("ex2.approx.ftz.f32 %0, %1;" : "=f"(y) : "f"(x)); return y;
}
__device__ __forceinline__ float rcpa(float x) {
    float y; asm("rcp.approx.ftz.f32 %0, %1;" : "=f"(y) : "f"(x)); return y;
}
__device__ __forceinline__ float tanha(float x) {
    float y; asm("tanh.approx.f32 %0, %1;" : "=f"(y) : "f"(x)); return y;
}
// exact-path sigmoid (2 MUFU) — spike output, error lands directly on out
__device__ __forceinline__ float sigm(float x) {
    return rcpa(1.0f + ex2a(-x * L2E));
}
// cheap sigmoid via tanh (1 MUFU) — compression mask, error attenuated >>1e3x
__device__ __forceinline__ float sigm_t(float x) {
    return fmaf(0.5f, tanha(0.5f * x), 0.5f);
}

__device__ __forceinline__ unsigned want_of(int k) { return (unsigned)((k + 1) & 1); }

__global__ void __launch_bounds__(NTHR, 1)
snn_etad_kernel(const float* __restrict__ x,
                const float* __restrict__ ac,
                const float* __restrict__ tw,
                const float* __restrict__ ig,
                const float* __restrict__ p_md,
                const float* __restrict__ p_sd,
                const float* __restrict__ p_th,
                float* __restrict__ out)
{
    extern __shared__ char smraw[];
    // c ping-pong: [2][NGRP][D4*2] half2 (fp16 compressed values)
    __half2* s_c  = (__half2*)smraw;                    // 2*7*1156 = 16184 half2
    __half2* s_ag = s_c + 2 * NGRP * D4 * 2;            // DD half2 {a, g}
    float*   s_rS = (float*)(s_ag + DD);                // 32
    float*   s_rW = s_rS + 32;                          // 32
    float*   s_rA = s_rW + 32;                          // 2 x 32 ping-pong
    float*   s_bsv = s_rA + 64;                         // 1
    volatile int* s_step = (volatile int*)(s_bsv + 1);  // 1

    const int tid  = threadIdx.x;
    const int grp  = tid >> 7;         // 0..6 row-group
    const int gtid = tid & 127;
    const int w    = tid >> 5;         // 0..27
    const int lane = tid & 31;

    int nrows = BB - NGRP * (int)blockIdx.x;
    nrows = nrows > NGRP ? NGRP : nrows;          // 7 or 2 (block 146)
    const bool rowact = grp < nrows;
    const int b = NGRP * blockIdx.x + grp;        // valid when rowact

    const float md = p_md[0];
    const float sd = p_sd[0];
    const float th = p_th[0];
    const float inv_bd = 1.0f / (float)(BB * DD);

    // Init per-feature gates (fp16 packed {a, g})
    for (int idx = tid; idx < DD; idx += NTHR) {
        const float a = ac[idx];
        const float g = sigm(tw[idx]) * sigm(ig[idx]);
        s_ag[idx] = __floats2half2_rn(a, g);
    }
    if (tid == 0) *s_step = 0;
    __syncthreads();

    // LIF state in registers (thread-private across all steps)
    float4 ir[NS4], vr[NS4];
#pragma unroll
    for (int s = 0; s < NS4; ++s) {
        ir[s] = make_float4(0.f, 0.f, 0.f, 0.f);
        vr[s] = make_float4(0.f, 0.f, 0.f, 0.f);
    }

    // ============ pass1+pass2 for timestep t: writes c(t) fp16 into ping-pong
    // slot (t&1), returns this warp's |c| sum (0 for inactive groups).
    auto compute_c = [&](int t) -> float {
        if (!rowact) return 0.0f;
        const float4* xrow4 = (const float4*)(x + ((size_t)t * BB + b) * DD);
        float4 xv[NS4];
        float S = 0.0f, W = 0.0f;
#pragma unroll
        for (int s = 0; s < NS4; ++s) {
            const int d4 = s * GSZ + gtid;
            const bool act = (s < NS4 - 1) || (gtid < TAIL4);
            if (act) {
                const float4 v = __ldg(xrow4 + d4);
                xv[s] = v;
                float e;
                e = ex2a(v.x * L2E); S += e; W += v.x * e;
                e = ex2a(v.y * L2E); S += e; W += v.y * e;
                e = ex2a(v.z * L2E); S += e; W += v.z * e;
                e = ex2a(v.w * L2E); S += e; W += v.w * e;
            }
        }
        S = warp_sum(S);
        W = warp_sum(W);
        if (lane == 0) { s_rS[w] = S; s_rW[w] = W; }
        asm volatile("bar.sync %0, %1;" :: "r"(grp + 1), "n"(GSZ) : "memory");
        S = s_rS[grp * 4 + 0] + s_rS[grp * 4 + 1] + s_rS[grp * 4 + 2] + s_rS[grp * 4 + 3];
        W = s_rW[grp * 4 + 0] + s_rW[grp * 4 + 1] + s_rW[grp * 4 + 2] + s_rW[grp * 4 + 3];
        // entropy = lnS - W/S - D*1e-8  (shift-invariant; |x|<~6 so no overflow)
        const float ent = __logf(S) - __fdividef(W, S) - (float)DD * 1e-8f;

        __half2* sc2 = s_c + ((unsigned)t & 1) * (NGRP * D4 * 2) + grp * (D4 * 2);
        float asum = 0.0f;
#pragma unroll
        for (int s = 0; s < NS4; ++s) {
            const int d4 = s * GSZ + gtid;
            const bool act = (s < NS4 - 1) || (gtid < TAIL4);
            if (act) {
                const uint4 agp = *(const uint4*)(s_ag + 4 * d4);
                const float2 ag0 = __half22float2(((const __half2*)&agp)[0]);
                const float2 ag1 = __half22float2(((const __half2*)&agp)[1]);
                const float2 ag2 = __half22float2(((const __half2*)&agp)[2]);
                const float2 ag3 = __half22float2(((const __half2*)&agp)[3]);
                float4 c = xv[s];
                c.x = c.x * sigm_t(ag0.x * ent) * ag0.y;
                c.y = c.y * sigm_t(ag1.x * ent) * ag1.y;
                c.z = c.z * sigm_t(ag2.x * ent) * ag2.y;
                c.w = c.w * sigm_t(ag3.x * ent) * ag3.y;
                sc2[d4 * 2 + 0] = __floats2half2_rn(c.x, c.y);
                sc2[d4 * 2 + 1] = __floats2half2_rn(c.z, c.w);
                asum += fabsf(c.x) + fabsf(c.y) + fabsf(c.z) + fabsf(c.w);
            }
        }
        return warp_sum(asum);
    };

    // ============ block-level |c| sum -> s_rA ping-pong + sync + warp0 reduce
    auto post_asum = [&](int k, float asum) -> float {
        if (lane == 0) s_rA[((unsigned)k & 1) * 32 + w] = asum;
        __syncthreads();
        float tot = 0.0f;
        if (w == 0) {
            const float vv = (lane < (NTHR / 32)) ? s_rA[((unsigned)k & 1) * 32 + lane] : 0.0f;
            tot = warp_sum(vv);
        }
        return tot;  // valid in warp 0 only
    };

    // ============ tid0: arrive at global barrier k with this block's total
    auto arrive = [&](int k, float tot) {
        atomicAdd(&g_bsum[k], tot);
        __threadfence();
        const unsigned pos = atomicAdd(&g_count, 1);
        if (pos == NBLK - 1) {
            atomicExch(&g_count, 0u);
            atomicExch(&g_bsum[(k + TT - 1) % TT], 0.0f);   // clean stale slot
            __threadfence();
            atomicExch(&g_sense, want_of(k));
        }
    };

    // ---------------- prologue: c(0) -> slot 0, arrive(0)
    {
        float asum = compute_c(0);
        float tot = post_asum(0, asum);
        if (tid == 0) arrive(0, tot);
    }

    for (int t = 0; t < TT; ++t) {
        // ---- pass1+2 for t+1 (independent of bs(t)) hides barrier latency
        float tot = 0.0f;
        const bool has_next = (t + 1) < TT;
        if (has_next) {
            float asum = compute_c(t + 1);
            tot = post_asum(t + 1, asum);
        } else {
            __syncthreads();
        }

        // ---- tid0: wait barrier t (released ~1 compute-iteration ago),
        //      publish bs(t), then arrive barrier t+1
        if (tid == 0) {
            const unsigned want = want_of(t);
            while (*((volatile unsigned*)&g_sense) != want) __nanosleep(32);
            __threadfence();
            const float bsv = atomicAdd(&g_bsum[t], 0.0f);   // coherent read
            *(volatile float*)s_bsv = bsv * inv_bd;
            __threadfence_block();
            *s_step = t + 1;                                  // publish
            if (has_next) arrive(t + 1, tot);
        }

        // ---- per-warp pickup (warps stagger straight into pass3)
        float bs;
        if (lane == 0) {
            while (*s_step < t + 1) { }
            bs = *(volatile float*)s_bsv;
        }
        bs = __shfl_sync(0xffffffffu, bs, 0);

        // ---- pass3: LIF on c(t) (fp16 ping-pong slot t&1), state in regs
        if (rowact) {
            const __half2* sc2 = s_c + ((unsigned)t & 1) * (NGRP * D4 * 2) + grp * (D4 * 2);
            float4* o4 = (float4*)(out + ((size_t)t * BB + b) * DD);
#pragma unroll
            for (int s = 0; s < NS4; ++s) {
                const int d4 = s * GSZ + gtid;
                const bool act = (s < NS4 - 1) || (gtid < TAIL4);
                if (act) {
                    const float2 c01 = __half22float2(sc2[d4 * 2 + 0]);
                    const float2 c23 = __half22float2(sc2[d4 * 2 + 1]);
                    float4 sp;

                    ir[s].x = sd * ir[s].x + c01.x * bs;
                    vr[s].x = md * vr[s].x + ir[s].x;
                    sp.x = sigm(vr[s].x - th);
                    vr[s].x -= sp.x * th;

                    ir[s].y = sd * ir[s].y + c01.y * bs;
                    vr[s].y = md * vr[s].y + ir[s].y;
                    sp.y = sigm(vr[s].y - th);
                    vr[s].y -= sp.y * th;

                    ir[s].z = sd * ir[s].z + c23.x * bs;
                    vr[s].z = md * vr[s].z + ir[s].z;
                    sp.z = sigm(vr[s].z - th);
                    vr[s].z -= sp.z * th;

                    ir[s].w = sd * ir[s].w + c23.y * bs;
                    vr[s].w = md * vr[s].w + ir[s].w;
                    sp.w = sigm(vr[s].w - th);
                    vr[s].w -= sp.w * th;

                    __stcs(o4 + d4, sp);
                }
            }
        }
        // smem reuse safety across steps:
        // - c ping-pong: pass2(t+1) writes slot (t+1)&1, pass3(t) reads slot
        //   t&1 (disjoint); slot reuse at t+2 is by the SAME thread that read
        //   it at t (thread-private mapping) -> program order suffices.
        // - s_rS/s_rW at step k+1 are rewritten only after this warp's s_step
        //   poll for step k passed; their step-k readers (same row-group)
        //   finished before post_asum(k)'s __syncthreads.
        // - s_rA is ping-ponged (same slot rewritten two barriers later).
        // - s_bsv/s_step are monotonic within a launch.
    }
}

extern "C" void kernel_launch(void* const* d_in, const int* in_sizes, int n_in,
                              void* d_out, int out_size)
{
    (void)in_sizes; (void)n_in; (void)out_size;
    const float* x  = (const float*)d_in[0];
    const float* ac = (const float*)d_in[1];
    const float* tw = (const float*)d_in[2];
    const float* ig = (const float*)d_in[3];
    const float* md = (const float*)d_in[4];
    const float* sd = (const float*)d_in[5];
    const float* th = (const float*)d_in[6];
    float* out = (float*)d_out;

    // bytes: c ping-pong 2*NGRP*D4*2 half2 *4B = 64736
    //      + ag DD half2 *4B = 9248
    //      + rS(32)+rW(32)+rA(64)+bsv(1)+step(1) floats = 520
    constexpr size_t SMEM_BYTES =
        (size_t)(2 * NGRP * D4 * 2) * 4 + (size_t)DD * 4 + 130 * 4;  // 74,504 B

    cudaFuncSetAttribute(snn_etad_kernel,
                         cudaFuncAttributeMaxDynamicSharedMemorySize,
                         (int)SMEM_BYTES);

    snn_etad_kernel<<<NBLK, NTHR, SMEM_BYTES>>>(x, ac, tw, ig, md, sd, th, out);
}